// round 3
// baseline (speedup 1.0000x reference)
#include <cuda_runtime.h>
#include <math.h>

// ---------------------------------------------------------------------------
// Problem constants (fixed by setup_inputs)
// ---------------------------------------------------------------------------
#define BB   2
#define SS   2048
#define HH   768
#define II   256
#define NHEADS_MAIN   12
#define NHEADS_SCORER 4
#define ALPHA 0.1f
#define EPSV  1e-8f

#define MROWS (BB*SS)          // 4096
#define MS    (MROWS*HH)       // 4096*768
#define ISZ   (MROWS*II)       // 4096*256

// scratch: q,k,v,attn,sqkv (5*MS) + h0,hatt,h2 (3*ISZ) + surv (MROWS)
__device__ float g_scr[5u*MS + 3u*ISZ + MROWS];

// ---------------------------------------------------------------------------
// Generic NT GEMM:  C[M,N] = A[M,K] @ W[N,K]^T + bias[N]   (optional relu)
// Tiles: BM=64, BN=64, BK=16; 128 threads; 8x4 micro-tile per thread.
// ---------------------------------------------------------------------------
__global__ __launch_bounds__(128)
void gemm_nt(const float* __restrict__ A, const float* __restrict__ W,
             const float* __restrict__ bias, float* __restrict__ C,
             int M, int N, int K, int act)
{
    __shared__ float As[16 * 68];
    __shared__ float Ws[16 * 68];

    const int t  = threadIdx.x;
    const int tx = t & 15;        // 16 col groups (4 cols each)
    const int ty = t >> 4;        // 8 row groups  (8 rows each)
    const int m0 = blockIdx.y * 64;
    const int n0 = blockIdx.x * 64;

    float acc[8][4];
#pragma unroll
    for (int i = 0; i < 8; i++)
#pragma unroll
        for (int j = 0; j < 4; j++) acc[i][j] = 0.f;

    for (int k0 = 0; k0 < K; k0 += 16) {
        // stage A and W tiles (transposed to [k][m]/[k][n]), float4 global loads
#pragma unroll
        for (int l = 0; l < 2; l++) {
            int fidx = t + l * 128;         // 256 float4 per operand
            int r    = fidx >> 2;           // 0..63 (row in tile)
            int k4   = (fidx & 3) << 2;     // 0,4,8,12
            float4 av = *reinterpret_cast<const float4*>(A + (size_t)(m0 + r) * K + k0 + k4);
            As[(k4 + 0) * 68 + r] = av.x;
            As[(k4 + 1) * 68 + r] = av.y;
            As[(k4 + 2) * 68 + r] = av.z;
            As[(k4 + 3) * 68 + r] = av.w;
            float4 wv = *reinterpret_cast<const float4*>(W + (size_t)(n0 + r) * K + k0 + k4);
            Ws[(k4 + 0) * 68 + r] = wv.x;
            Ws[(k4 + 1) * 68 + r] = wv.y;
            Ws[(k4 + 2) * 68 + r] = wv.z;
            Ws[(k4 + 3) * 68 + r] = wv.w;
        }
        __syncthreads();

#pragma unroll
        for (int k = 0; k < 16; k++) {
            float4 a0 = *reinterpret_cast<const float4*>(&As[k * 68 + ty * 8]);
            float4 a1 = *reinterpret_cast<const float4*>(&As[k * 68 + ty * 8 + 4]);
            float4 wv = *reinterpret_cast<const float4*>(&Ws[k * 68 + tx * 4]);
            float a[8] = {a0.x, a0.y, a0.z, a0.w, a1.x, a1.y, a1.z, a1.w};
            float w[4] = {wv.x, wv.y, wv.z, wv.w};
#pragma unroll
            for (int i = 0; i < 8; i++)
#pragma unroll
                for (int j = 0; j < 4; j++) acc[i][j] += a[i] * w[j];
        }
        __syncthreads();
    }

    // epilogue
    const int col = n0 + tx * 4;
    float4 bv = *reinterpret_cast<const float4*>(bias + col);
#pragma unroll
    for (int i = 0; i < 8; i++) {
        int row = m0 + ty * 8 + i;
        float4 o;
        o.x = acc[i][0] + bv.x;
        o.y = acc[i][1] + bv.y;
        o.z = acc[i][2] + bv.z;
        o.w = acc[i][3] + bv.w;
        if (act) {
            o.x = fmaxf(o.x, 0.f); o.y = fmaxf(o.y, 0.f);
            o.z = fmaxf(o.z, 0.f); o.w = fmaxf(o.w, 0.f);
        }
        *reinterpret_cast<float4*>(C + (size_t)row * N + col) = o;
    }
}

// ---------------------------------------------------------------------------
// Flash attention (fp32, head_dim = 64), online softmax, additive key bias:
//   bias_k = alpha*surv[k] (if surv) + (mask[k] ? 0 : -1e9)
// Q is pre-scaled by 1/8 at load. Grid: (S/64, B*nh). 128 threads.
// Thread map: ty=t>>3 (4 rows: ty*4..), tx=t&7 (8 cols/dims: tx, tx+8, ..)
// All smem strides 68 words (272B = 17*16B): LDS.128-aligned, and K-loads
// cover banks 4*tx..4*tx+3 -> all 32 banks, conflict-free.
// ---------------------------------------------------------------------------
#define QS_STRIDE 68
#define KS_STRIDE 68
#define PS_STRIDE 68
#define FA_SMEM   ((64*QS_STRIDE + 2*64*KS_STRIDE + 64*PS_STRIDE) * 4)

__global__ __launch_bounds__(128)
void flash_attn(const float* __restrict__ Q, const float* __restrict__ K,
                const float* __restrict__ V, float* __restrict__ O,
                const int* __restrict__ mask, const float* __restrict__ surv,
                float alpha, int S, int qstride, int ostride, int nh)
{
    extern __shared__ float sm[];
    float* Qs = sm;                         // [64][68]
    float* Ks = Qs + 64 * QS_STRIDE;        // [64][68]
    float* Vs = Ks + 64 * KS_STRIDE;        // [64][68]
    float* Ps = Vs + 64 * KS_STRIDE;        // [64][68]

    const int t  = threadIdx.x;
    const int tx = t & 7;
    const int ty = t >> 3;
    const int bh = blockIdx.y;
    const int b  = bh / nh;
    const int h  = bh % nh;
    const int row0 = blockIdx.x * 64;
    const float scale = 0.125f;   // 1/sqrt(64)

    const float* Qb = Q + ((size_t)(b * S + row0)) * qstride + h * 64;
    const float* Kb = K + ((size_t)b * S) * qstride + h * 64;
    const float* Vb = V + ((size_t)b * S) * qstride + h * 64;
    float*       Ob = O + ((size_t)(b * S + row0)) * ostride + h * 64;
    const int*   mb = mask + b * S;
    const float* sb = surv ? (surv + b * S) : (const float*)0;

    // load Q tile, pre-scaled (float4 path: 8 x 128 lanes x 16B = 64x64 tile)
#pragma unroll
    for (int l = 0; l < 8; l++) {
        int fidx = t + l * 128;
        int r  = fidx >> 4;
        int c4 = (fidx & 15) << 2;
        float4 qv = *reinterpret_cast<const float4*>(Qb + (size_t)r * qstride + c4);
        Qs[r * QS_STRIDE + c4 + 0] = qv.x * scale;
        Qs[r * QS_STRIDE + c4 + 1] = qv.y * scale;
        Qs[r * QS_STRIDE + c4 + 2] = qv.z * scale;
        Qs[r * QS_STRIDE + c4 + 3] = qv.w * scale;
    }

    float m_i[4], l_i[4], acc[4][8];
#pragma unroll
    for (int i = 0; i < 4; i++) {
        m_i[i] = -1e30f; l_i[i] = 0.f;
#pragma unroll
        for (int j = 0; j < 8; j++) acc[i][j] = 0.f;
    }
    __syncthreads();

    for (int k0 = 0; k0 < S; k0 += 64) {
        // stage K and V tiles (float4)
#pragma unroll
        for (int l = 0; l < 8; l++) {
            int fidx = t + l * 128;
            int r  = fidx >> 4;
            int c4 = (fidx & 15) << 2;
            float4 kv = *reinterpret_cast<const float4*>(Kb + (size_t)(k0 + r) * qstride + c4);
            *reinterpret_cast<float4*>(&Ks[r * KS_STRIDE + c4]) = kv;
            float4 vv = *reinterpret_cast<const float4*>(Vb + (size_t)(k0 + r) * qstride + c4);
            *reinterpret_cast<float4*>(&Vs[r * KS_STRIDE + c4]) = vv;
        }
        __syncthreads();

        // per-key additive bias for this thread's 8 columns
        float s[4][8];
        {
            float bias[8];
#pragma unroll
            for (int j = 0; j < 8; j++) {
                int key = k0 + tx + j * 8;
                float bb = mb[key] ? 0.f : -1e9f;
                if (sb) bb += alpha * sb[key];
                bias[j] = bb;
            }
#pragma unroll
            for (int i = 0; i < 4; i++)
#pragma unroll
                for (int j = 0; j < 8; j++) s[i][j] = bias[j];
        }

        // S = (Q*scale) @ K^T  -- dot-product form, d in float4 quads.
        // Per quad: 12 LDS.128 + 128 FFMA (~91% FMA issue).
#pragma unroll 2
        for (int d4 = 0; d4 < 64; d4 += 4) {
            float4 qv0 = *reinterpret_cast<const float4*>(&Qs[(ty * 4 + 0) * QS_STRIDE + d4]);
            float4 qv1 = *reinterpret_cast<const float4*>(&Qs[(ty * 4 + 1) * QS_STRIDE + d4]);
            float4 qv2 = *reinterpret_cast<const float4*>(&Qs[(ty * 4 + 2) * QS_STRIDE + d4]);
            float4 qv3 = *reinterpret_cast<const float4*>(&Qs[(ty * 4 + 3) * QS_STRIDE + d4]);
#pragma unroll
            for (int j = 0; j < 8; j++) {
                float4 kv = *reinterpret_cast<const float4*>(&Ks[(tx + j * 8) * KS_STRIDE + d4]);
                s[0][j] += qv0.x * kv.x + qv0.y * kv.y + qv0.z * kv.z + qv0.w * kv.w;
                s[1][j] += qv1.x * kv.x + qv1.y * kv.y + qv1.z * kv.z + qv1.w * kv.w;
                s[2][j] += qv2.x * kv.x + qv2.y * kv.y + qv2.z * kv.z + qv2.w * kv.w;
                s[3][j] += qv3.x * kv.x + qv3.y * kv.y + qv3.z * kv.z + qv3.w * kv.w;
            }
        }

        // online softmax (row reductions over the 8 tx lanes)
#pragma unroll
        for (int i = 0; i < 4; i++) {
            float mx = s[i][0];
#pragma unroll
            for (int j = 1; j < 8; j++) mx = fmaxf(mx, s[i][j]);
            mx = fmaxf(mx, __shfl_xor_sync(0xffffffffu, mx, 1));
            mx = fmaxf(mx, __shfl_xor_sync(0xffffffffu, mx, 2));
            mx = fmaxf(mx, __shfl_xor_sync(0xffffffffu, mx, 4));
            float mnew = fmaxf(m_i[i], mx);
            float corr = __expf(m_i[i] - mnew);
            m_i[i] = mnew;
            float sum = 0.f;
#pragma unroll
            for (int j = 0; j < 8; j++) {
                float p = __expf(s[i][j] - mnew);
                s[i][j] = p;
                sum += p;
            }
            sum += __shfl_xor_sync(0xffffffffu, sum, 1);
            sum += __shfl_xor_sync(0xffffffffu, sum, 2);
            sum += __shfl_xor_sync(0xffffffffu, sum, 4);
            l_i[i] = l_i[i] * corr + sum;
#pragma unroll
            for (int j = 0; j < 8; j++) acc[i][j] *= corr;
#pragma unroll
            for (int j = 0; j < 8; j++)
                Ps[(ty * 4 + i) * PS_STRIDE + tx + j * 8] = s[i][j];
        }
        __syncthreads();

        // O += P @ V  -- kk in quads, P via LDS.128, V scalar (conflict-free)
#pragma unroll 2
        for (int kk = 0; kk < 64; kk += 4) {
            float4 p0 = *reinterpret_cast<const float4*>(&Ps[(ty * 4 + 0) * PS_STRIDE + kk]);
            float4 p1 = *reinterpret_cast<const float4*>(&Ps[(ty * 4 + 1) * PS_STRIDE + kk]);
            float4 p2 = *reinterpret_cast<const float4*>(&Ps[(ty * 4 + 2) * PS_STRIDE + kk]);
            float4 p3 = *reinterpret_cast<const float4*>(&Ps[(ty * 4 + 3) * PS_STRIDE + kk]);
            float pa[4][4] = {{p0.x, p0.y, p0.z, p0.w},
                              {p1.x, p1.y, p1.z, p1.w},
                              {p2.x, p2.y, p2.z, p2.w},
                              {p3.x, p3.y, p3.z, p3.w}};
#pragma unroll
            for (int q = 0; q < 4; q++) {
#pragma unroll
                for (int j = 0; j < 8; j++) {
                    float vv = Vs[(kk + q) * KS_STRIDE + tx + j * 8];
                    acc[0][j] += pa[0][q] * vv;
                    acc[1][j] += pa[1][q] * vv;
                    acc[2][j] += pa[2][q] * vv;
                    acc[3][j] += pa[3][q] * vv;
                }
            }
        }
        __syncthreads();
    }

    // write output
#pragma unroll
    for (int i = 0; i < 4; i++) {
        float inv = 1.f / l_i[i];
#pragma unroll
        for (int j = 0; j < 8; j++)
            Ob[(size_t)(ty * 4 + i) * ostride + tx + j * 8] = acc[i][j] * inv;
    }
}

// ---------------------------------------------------------------------------
// Fused MLP heads + survival score:
//   n     = softplus(w2n . relu(W1n h + b1n) + b2n)
//   mu    = sigmoid (w2m . relu(W1m h + b1m) + b2m)
//   delta = relu    (w2d . relu(W1d h + b1d) + b2d)
//   surv  = log(n+eps) + log(mu+eps) - delta
// h: [4096, 256]. 16 rows per block, 128 threads (one hidden unit each).
// ---------------------------------------------------------------------------
__global__ __launch_bounds__(128)
void mlp_heads(const float* __restrict__ h,
               const float* __restrict__ nw1, const float* __restrict__ nb1,
               const float* __restrict__ nw2, const float* __restrict__ nb2,
               const float* __restrict__ mw1, const float* __restrict__ mb1,
               const float* __restrict__ mw2, const float* __restrict__ mb2,
               const float* __restrict__ dw1, const float* __restrict__ db1,
               const float* __restrict__ dw2, const float* __restrict__ db2,
               float* __restrict__ surv)
{
    __shared__ float hs[16 * 256];      // 16 rows of h
    __shared__ float ws[128 * 33];      // weight chunk [128 units][32 k] padded
    __shared__ float red[16 * 128];     // per-row reduction
    __shared__ float bres[3][16];

    const int t  = threadIdx.x;
    const int r0 = blockIdx.x * 16;

#pragma unroll
    for (int l = 0; l < 32; l++) {
        int idx = t + l * 128;
        int r = idx >> 8, c = idx & 255;
        hs[r * 256 + c] = h[(size_t)(r0 + r) * 256 + c];
    }
    __syncthreads();

    for (int br = 0; br < 3; br++) {
        const float* w1 = (br == 0) ? nw1 : (br == 1) ? mw1 : dw1;
        const float* b1 = (br == 0) ? nb1 : (br == 1) ? mb1 : db1;
        const float* w2 = (br == 0) ? nw2 : (br == 1) ? mw2 : dw2;
        const float* b2 = (br == 0) ? nb2 : (br == 1) ? mb2 : db2;

        float acc[16];
        float bb = b1[t];
#pragma unroll
        for (int r = 0; r < 16; r++) acc[r] = bb;

        for (int c0 = 0; c0 < 256; c0 += 32) {
            __syncthreads();   // protect ws reuse
#pragma unroll
            for (int l = 0; l < 8; l++) {
                int fidx = t + l * 128;           // 1024 float4 = 128x32 floats
                int row = fidx >> 3;
                int k4  = (fidx & 7) << 2;
                float4 wv = *reinterpret_cast<const float4*>(w1 + (size_t)row * 256 + c0 + k4);
                ws[row * 33 + k4 + 0] = wv.x;
                ws[row * 33 + k4 + 1] = wv.y;
                ws[row * 33 + k4 + 2] = wv.z;
                ws[row * 33 + k4 + 3] = wv.w;
            }
            __syncthreads();
#pragma unroll
            for (int kk = 0; kk < 32; kk++) {
                float wv = ws[t * 33 + kk];
#pragma unroll
                for (int r = 0; r < 16; r++)
                    acc[r] += wv * hs[r * 256 + c0 + kk];
            }
        }

        float w2v = w2[t];
#pragma unroll
        for (int r = 0; r < 16; r++)
            red[r * 128 + t] = fmaxf(acc[r], 0.f) * w2v;
        __syncthreads();
        for (int st = 64; st > 0; st >>= 1) {
            if (t < st) {
#pragma unroll
                for (int r = 0; r < 16; r++)
                    red[r * 128 + t] += red[r * 128 + t + st];
            }
            __syncthreads();
        }
        if (t < 16) {
            float x = red[t * 128] + b2[0];
            float y;
            if (br == 0) {
                y = (x > 20.f) ? x : log1pf(expf(x));          // softplus
            } else if (br == 1) {
                y = 1.f / (1.f + expf(-x));                    // sigmoid
            } else {
                y = fmaxf(x, 0.f);                             // relu
            }
            bres[br][t] = y;
        }
        __syncthreads();
    }

    if (t < 16)
        surv[r0 + t] = logf(bres[0][t] + EPSV) + logf(bres[1][t] + EPSV) - bres[2][t];
}

// ---------------------------------------------------------------------------
// Host launch
// ---------------------------------------------------------------------------
extern "C" void kernel_launch(void* const* d_in, const int* in_sizes, int n_in,
                              void* d_out, int out_size)
{
    const float* x      = (const float*)d_in[0];
    const int*   mask   = (const int*)  d_in[1];
    const float* qw     = (const float*)d_in[2];
    const float* qb     = (const float*)d_in[3];
    const float* kw     = (const float*)d_in[4];
    const float* kb     = (const float*)d_in[5];
    const float* vw     = (const float*)d_in[6];
    const float* vb     = (const float*)d_in[7];
    const float* ow     = (const float*)d_in[8];
    const float* ob     = (const float*)d_in[9];
    const float* sp_w   = (const float*)d_in[10];
    const float* sp_b   = (const float*)d_in[11];
    const float* sa_in_w  = (const float*)d_in[12];
    const float* sa_in_b  = (const float*)d_in[13];
    const float* sa_out_w = (const float*)d_in[14];
    const float* sa_out_b = (const float*)d_in[15];
    const float* nw1 = (const float*)d_in[16];
    const float* nb1 = (const float*)d_in[17];
    const float* nw2 = (const float*)d_in[18];
    const float* nb2 = (const float*)d_in[19];
    const float* mw1 = (const float*)d_in[20];
    const float* mb1 = (const float*)d_in[21];
    const float* mw2 = (const float*)d_in[22];
    const float* mb2 = (const float*)d_in[23];
    const float* dw1 = (const float*)d_in[24];
    const float* db1 = (const float*)d_in[25];
    const float* dw2 = (const float*)d_in[26];
    const float* db2 = (const float*)d_in[27];

    float* out = (float*)d_out;

    float* scr = 0;
    cudaGetSymbolAddress((void**)&scr, g_scr);
    float* q    = scr;
    float* k    = q    + MS;
    float* v    = k    + MS;
    float* attn = v    + MS;
    float* sqkv = attn + MS;
    float* h0   = sqkv + MS;
    float* hatt = h0   + ISZ;
    float* h2   = hatt + ISZ;
    float* surv = h2   + ISZ;

    cudaFuncSetAttribute(flash_attn, cudaFuncAttributeMaxDynamicSharedMemorySize, FA_SMEM);

    const int M = MROWS;   // 4096

    // ---- scorer branch (needed before main attention) ----
    // h0 = x @ sp_w^T + sp_b                      [4096, 256]
    gemm_nt<<<dim3(II / 64, M / 64), 128>>>(x, sp_w, sp_b, h0, M, II, HH, 0);
    // sqkv = h0 @ sa_in_w^T + sa_in_b             [4096, 768]
    gemm_nt<<<dim3(HH / 64, M / 64), 128>>>(h0, sa_in_w, sa_in_b, sqkv, M, HH, II, 0);
    // scorer self-attention (4 heads, dim 64)     -> hatt [4096, 256]
    flash_attn<<<dim3(SS / 64, BB * NHEADS_SCORER), 128, FA_SMEM>>>(
        sqkv + 0, sqkv + II, sqkv + 2 * II, hatt,
        mask, (const float*)0, 0.f, SS, /*qstride=*/3 * II, /*ostride=*/II, NHEADS_SCORER);
    // h2 = hatt @ sa_out_w^T + sa_out_b           [4096, 256]
    gemm_nt<<<dim3(II / 64, M / 64), 128>>>(hatt, sa_out_w, sa_out_b, h2, M, II, II, 0);
    // surv = log(n+eps)+log(mu+eps)-delta         [4096]
    mlp_heads<<<M / 16, 128>>>(h2, nw1, nb1, nw2, nb2, mw1, mb1, mw2, mb2,
                               dw1, db1, dw2, db2, surv);

    // ---- main branch ----
    gemm_nt<<<dim3(HH / 64, M / 64), 128>>>(x, qw, qb, q, M, HH, HH, 0);
    gemm_nt<<<dim3(HH / 64, M / 64), 128>>>(x, kw, kb, k, M, HH, HH, 0);
    gemm_nt<<<dim3(HH / 64, M / 64), 128>>>(x, vw, vb, v, M, HH, HH, 0);

    // main attention with survival bias           -> attn [4096, 768]
    flash_attn<<<dim3(SS / 64, BB * NHEADS_MAIN), 128, FA_SMEM>>>(
        q, k, v, attn, mask, surv, ALPHA, SS, /*qstride=*/HH, /*ostride=*/HH, NHEADS_MAIN);

    // output projection                           -> d_out [4096, 768]
    gemm_nt<<<dim3(HH / 64, M / 64), 128>>>(attn, ow, ob, out, M, HH, HH, 0);
}

// round 16
// speedup vs baseline: 1.5062x; 1.5062x over previous
#include <cuda_runtime.h>
#include <math.h>

// ---------------------------------------------------------------------------
// Problem constants (fixed by setup_inputs)
// ---------------------------------------------------------------------------
#define BB   2
#define SS   2048
#define HH   768
#define II   256
#define NHEADS_MAIN   12
#define NHEADS_SCORER 4
#define ALPHA 0.1f
#define EPSV  1e-8f

#define MROWS (BB*SS)          // 4096
#define MS    (MROWS*HH)       // 4096*768
#define ISZ   (MROWS*II)       // 4096*256

// scratch: q,k,v,attn,sqkv (5*MS) + h0,hatt,h2 (3*ISZ) + surv (MROWS)
__device__ float g_scr[5u*MS + 3u*ISZ + MROWS];

// ---------------------------------------------------------------------------
// tf32 mma.sync helpers (m16n8k8, row.col). tf32x3 error compensation:
//   a = a_hi + a_lo (13-bit split), D += Ah*Bl + Al*Bh + Ah*Bh
// ---------------------------------------------------------------------------
__device__ __forceinline__ void mma_tf32(float d[4], const unsigned a[4], const unsigned b[2]) {
    asm volatile(
        "mma.sync.aligned.m16n8k8.row.col.f32.tf32.tf32.f32 "
        "{%0,%1,%2,%3}, {%4,%5,%6,%7}, {%8,%9}, {%0,%1,%2,%3};\n"
        : "+f"(d[0]), "+f"(d[1]), "+f"(d[2]), "+f"(d[3])
        : "r"(a[0]), "r"(a[1]), "r"(a[2]), "r"(a[3]), "r"(b[0]), "r"(b[1]));
}

__device__ __forceinline__ void split1(float x, unsigned& hi, unsigned& lo) {
    unsigned xb = __float_as_uint(x) & 0xffffe000u;   // truncate to tf32 grid
    hi = xb;
    lo = __float_as_uint(x - __uint_as_float(xb));    // exact residual (<=13 bits)
}

// ---------------------------------------------------------------------------
// tf32x3 NT GEMM:  C[M,N] = A[M,K] @ W[N,K]^T + bias[N]
// BM=128, BN=64, BK=32; 256 threads = 8 warps (4 m-quads x 2 n-halves),
// each warp computes 32x32 via 2x4 m16n8k8 fragments.
// smem stride 36 words: (36g+tg) mod 32 = 4g+tg -> conflict-free frag loads.
// ---------------------------------------------------------------------------
#define GA_STRIDE 36
__global__ __launch_bounds__(256)
void gemm_tf32(const float* __restrict__ A, const float* __restrict__ W,
               const float* __restrict__ bias, float* __restrict__ C,
               int M, int N, int K)
{
    __shared__ float As[128 * GA_STRIDE];
    __shared__ float Ws[64 * GA_STRIDE];

    const int t    = threadIdx.x;
    const int lane = t & 31, w = t >> 5;
    const int g    = lane >> 2, tg = lane & 3;
    const int wm   = w & 3, wn = w >> 2;
    const int m0   = blockIdx.y * 128, n0 = blockIdx.x * 64;

    float acc[2][4][4];
#pragma unroll
    for (int mi = 0; mi < 2; mi++)
#pragma unroll
        for (int ni = 0; ni < 4; ni++)
#pragma unroll
            for (int r = 0; r < 4; r++) acc[mi][ni][r] = 0.f;

    const int arow = wm * 32 + g;   // + mi*16 (+8)
    const int brow = wn * 32 + g;   // + ni*8

    for (int k0 = 0; k0 < K; k0 += 32) {
        // stage A (128x32) and W (64x32): float4 loads, 4+2 per thread
#pragma unroll
        for (int li = 0; li < 4; li++) {
            int fidx = t + li * 256;
            int r = fidx >> 3, c4 = (fidx & 7) << 2;
            *reinterpret_cast<float4*>(&As[r * GA_STRIDE + c4]) =
                *reinterpret_cast<const float4*>(A + (size_t)(m0 + r) * K + k0 + c4);
        }
#pragma unroll
        for (int li = 0; li < 2; li++) {
            int fidx = t + li * 256;
            int r = fidx >> 3, c4 = (fidx & 7) << 2;
            *reinterpret_cast<float4*>(&Ws[r * GA_STRIDE + c4]) =
                *reinterpret_cast<const float4*>(W + (size_t)(n0 + r) * K + k0 + c4);
        }
        __syncthreads();

#pragma unroll
        for (int kk = 0; kk < 32; kk += 8) {
            unsigned ah[2][4], al[2][4];
#pragma unroll
            for (int mi = 0; mi < 2; mi++) {
                const float* base = &As[(arow + mi * 16) * GA_STRIDE + kk + tg];
                split1(base[0],                  ah[mi][0], al[mi][0]);
                split1(base[8 * GA_STRIDE],      ah[mi][1], al[mi][1]);
                split1(base[4],                  ah[mi][2], al[mi][2]);
                split1(base[8 * GA_STRIDE + 4],  ah[mi][3], al[mi][3]);
            }
            unsigned bh2[4][2], bl2[4][2];
#pragma unroll
            for (int ni = 0; ni < 4; ni++) {
                const float* base = &Ws[(brow + ni * 8) * GA_STRIDE + kk + tg];
                split1(base[0], bh2[ni][0], bl2[ni][0]);
                split1(base[4], bh2[ni][1], bl2[ni][1]);
            }
#pragma unroll
            for (int mi = 0; mi < 2; mi++)
#pragma unroll
                for (int ni = 0; ni < 4; ni++) {
                    mma_tf32(acc[mi][ni], ah[mi], bl2[ni]);
                    mma_tf32(acc[mi][ni], al[mi], bh2[ni]);
                    mma_tf32(acc[mi][ni], ah[mi], bh2[ni]);
                }
        }
        __syncthreads();
    }

    // epilogue: bias + store (float2 per fragment row)
#pragma unroll
    for (int mi = 0; mi < 2; mi++)
#pragma unroll
        for (int ni = 0; ni < 4; ni++) {
            int row = m0 + arow + mi * 16;
            int col = n0 + wn * 32 + ni * 8 + 2 * tg;
            float2 bv = *reinterpret_cast<const float2*>(bias + col);
            float2 v0 = make_float2(acc[mi][ni][0] + bv.x, acc[mi][ni][1] + bv.y);
            float2 v1 = make_float2(acc[mi][ni][2] + bv.x, acc[mi][ni][3] + bv.y);
            *reinterpret_cast<float2*>(C + (size_t)row * N + col) = v0;
            *reinterpret_cast<float2*>(C + (size_t)(row + 8) * N + col) = v1;
        }
}

// ---------------------------------------------------------------------------
// tf32x3 flash attention (head_dim=64), online softmax, additive key bias:
//   bias_k = alpha*surv[k] (if surv) + (mask[k] ? 0 : -1e9)
// 128 threads = 4 warps; warp w owns query rows 16w..16w+15.
// Strides chosen for conflict-free fragment access:
//   Qs/Ks 68 (4g+tg), Vs 72 (8tg+g), Ps 76 (12g+tg mod 32 all distinct).
// ---------------------------------------------------------------------------
#define FQ_STR 68
#define FK_STR 68
#define FV_STR 72
#define FP_STR 76
#define FA_FLOATS (64*FQ_STR + 64*FK_STR + 64*FV_STR + 64*FP_STR + 64)
#define FA_SMEM   (FA_FLOATS * 4)

__global__ __launch_bounds__(128)
void flash_tf32(const float* __restrict__ Q, const float* __restrict__ K,
                const float* __restrict__ V, float* __restrict__ O,
                const int* __restrict__ mask, const float* __restrict__ surv,
                float alpha, int S, int qstride, int ostride, int nh)
{
    extern __shared__ float smf[];
    float* Qs     = smf;
    float* Ks     = Qs + 64 * FQ_STR;
    float* Vs     = Ks + 64 * FK_STR;
    float* Ps     = Vs + 64 * FV_STR;
    float* bias_s = Ps + 64 * FP_STR;

    const int t    = threadIdx.x;
    const int lane = t & 31, w = t >> 5;
    const int g    = lane >> 2, tg = lane & 3;
    const int bhid = blockIdx.y, b = bhid / nh, h = bhid % nh;
    const int row0 = blockIdx.x * 64;

    const float* Qb = Q + (size_t)(b * S + row0) * qstride + h * 64;
    const float* Kb = K + (size_t)(b * S) * qstride + h * 64;
    const float* Vb = V + (size_t)(b * S) * qstride + h * 64;
    float*       Ob = O + (size_t)(b * S + row0) * ostride + h * 64;
    const int*   mb = mask + b * S;
    const float* sb = surv ? (surv + b * S) : (const float*)0;

    // stage Q once, pre-scaled by 1/sqrt(64)
#pragma unroll
    for (int li = 0; li < 8; li++) {
        int fidx = t + li * 128;
        int r = fidx >> 4, c4 = (fidx & 15) << 2;
        float4 qv = *reinterpret_cast<const float4*>(Qb + (size_t)r * qstride + c4);
        Qs[r * FQ_STR + c4 + 0] = qv.x * 0.125f;
        Qs[r * FQ_STR + c4 + 1] = qv.y * 0.125f;
        Qs[r * FQ_STR + c4 + 2] = qv.z * 0.125f;
        Qs[r * FQ_STR + c4 + 3] = qv.w * 0.125f;
    }

    const int qr = w * 16 + g;   // fragment base row (and qr+8)

    float mrow0 = -1e30f, mrow1 = -1e30f, lrow0 = 0.f, lrow1 = 0.f;
    float o[8][4];
#pragma unroll
    for (int di = 0; di < 8; di++)
#pragma unroll
        for (int r = 0; r < 4; r++) o[di][r] = 0.f;

    for (int k0 = 0; k0 < S; k0 += 64) {
        // stage K and V tiles
#pragma unroll
        for (int li = 0; li < 8; li++) {
            int fidx = t + li * 128;
            int r = fidx >> 4, c4 = (fidx & 15) << 2;
            *reinterpret_cast<float4*>(&Ks[r * FK_STR + c4]) =
                *reinterpret_cast<const float4*>(Kb + (size_t)(k0 + r) * qstride + c4);
            *reinterpret_cast<float4*>(&Vs[r * FV_STR + c4]) =
                *reinterpret_cast<const float4*>(Vb + (size_t)(k0 + r) * qstride + c4);
        }
        if (t < 64) {
            int key = k0 + t;
            float bv = mb[key] ? 0.f : -1e9f;
            if (sb) bv += alpha * sb[key];
            bias_s[t] = bv;
        }
        __syncthreads();

        // ---- S = (Q/8) @ K^T  (tf32x3) ----
        float s[8][4];
#pragma unroll
        for (int ni = 0; ni < 8; ni++)
#pragma unroll
            for (int r = 0; r < 4; r++) s[ni][r] = 0.f;

#pragma unroll 2
        for (int k8 = 0; k8 < 64; k8 += 8) {
            unsigned qh[4], ql[4];
            const float* qbase = &Qs[qr * FQ_STR + k8 + tg];
            split1(qbase[0],                 qh[0], ql[0]);
            split1(qbase[8 * FQ_STR],        qh[1], ql[1]);
            split1(qbase[4],                 qh[2], ql[2]);
            split1(qbase[8 * FQ_STR + 4],    qh[3], ql[3]);
#pragma unroll
            for (int ni = 0; ni < 8; ni++) {
                unsigned kh[2], kl[2];
                const float* kbase = &Ks[(ni * 8 + g) * FK_STR + k8 + tg];
                split1(kbase[0], kh[0], kl[0]);
                split1(kbase[4], kh[1], kl[1]);
                mma_tf32(s[ni], qh, kl);
                mma_tf32(s[ni], ql, kh);
                mma_tf32(s[ni], qh, kh);
            }
        }

        // ---- bias + online softmax (rows qr, qr+8; reduce over tg group) ----
        float mx0 = -1e30f, mx1 = -1e30f;
#pragma unroll
        for (int ni = 0; ni < 8; ni++) {
            float2 bv = *reinterpret_cast<const float2*>(&bias_s[ni * 8 + 2 * tg]);
            s[ni][0] += bv.x; s[ni][1] += bv.y;
            s[ni][2] += bv.x; s[ni][3] += bv.y;
            mx0 = fmaxf(mx0, fmaxf(s[ni][0], s[ni][1]));
            mx1 = fmaxf(mx1, fmaxf(s[ni][2], s[ni][3]));
        }
        mx0 = fmaxf(mx0, __shfl_xor_sync(0xffffffffu, mx0, 1));
        mx0 = fmaxf(mx0, __shfl_xor_sync(0xffffffffu, mx0, 2));
        mx1 = fmaxf(mx1, __shfl_xor_sync(0xffffffffu, mx1, 1));
        mx1 = fmaxf(mx1, __shfl_xor_sync(0xffffffffu, mx1, 2));

        float mn0 = fmaxf(mrow0, mx0), mn1 = fmaxf(mrow1, mx1);
        float cr0 = __expf(mrow0 - mn0), cr1 = __expf(mrow1 - mn1);
        mrow0 = mn0; mrow1 = mn1;

        float sum0 = 0.f, sum1 = 0.f;
#pragma unroll
        for (int ni = 0; ni < 8; ni++) {
            s[ni][0] = __expf(s[ni][0] - mn0);
            s[ni][1] = __expf(s[ni][1] - mn0);
            s[ni][2] = __expf(s[ni][2] - mn1);
            s[ni][3] = __expf(s[ni][3] - mn1);
            sum0 += s[ni][0] + s[ni][1];
            sum1 += s[ni][2] + s[ni][3];
            *reinterpret_cast<float2*>(&Ps[qr * FP_STR + ni * 8 + 2 * tg]) =
                make_float2(s[ni][0], s[ni][1]);
            *reinterpret_cast<float2*>(&Ps[(qr + 8) * FP_STR + ni * 8 + 2 * tg]) =
                make_float2(s[ni][2], s[ni][3]);
        }
        sum0 += __shfl_xor_sync(0xffffffffu, sum0, 1);
        sum0 += __shfl_xor_sync(0xffffffffu, sum0, 2);
        sum1 += __shfl_xor_sync(0xffffffffu, sum1, 1);
        sum1 += __shfl_xor_sync(0xffffffffu, sum1, 2);
        lrow0 = lrow0 * cr0 + sum0;
        lrow1 = lrow1 * cr1 + sum1;

#pragma unroll
        for (int di = 0; di < 8; di++) {
            o[di][0] *= cr0; o[di][1] *= cr0;
            o[di][2] *= cr1; o[di][3] *= cr1;
        }
        __syncwarp();   // P stores visible across lanes of this warp

        // ---- O += P @ V  (tf32x3) ----
#pragma unroll 2
        for (int k8 = 0; k8 < 64; k8 += 8) {
            unsigned ph[4], pl[4];
            const float* pbase = &Ps[qr * FP_STR + k8 + tg];
            split1(pbase[0],              ph[0], pl[0]);
            split1(pbase[8 * FP_STR],     ph[1], pl[1]);
            split1(pbase[4],              ph[2], pl[2]);
            split1(pbase[8 * FP_STR + 4], ph[3], pl[3]);
#pragma unroll
            for (int di = 0; di < 8; di++) {
                unsigned vh[2], vl[2];
                const float* vbase = &Vs[(k8 + tg) * FV_STR + di * 8 + g];
                split1(vbase[0],          vh[0], vl[0]);
                split1(vbase[4 * FV_STR], vh[1], vl[1]);
                mma_tf32(o[di], ph, vl);
                mma_tf32(o[di], pl, vh);
                mma_tf32(o[di], ph, vh);
            }
        }
        __syncthreads();   // protect K/V/bias restaging
    }

    // ---- write normalized output ----
    float inv0 = 1.f / lrow0, inv1 = 1.f / lrow1;
#pragma unroll
    for (int di = 0; di < 8; di++) {
        *reinterpret_cast<float2*>(Ob + (size_t)qr * ostride + di * 8 + 2 * tg) =
            make_float2(o[di][0] * inv0, o[di][1] * inv0);
        *reinterpret_cast<float2*>(Ob + (size_t)(qr + 8) * ostride + di * 8 + 2 * tg) =
            make_float2(o[di][2] * inv1, o[di][3] * inv1);
    }
}

// ---------------------------------------------------------------------------
// Fused MLP heads + survival score.
// ---------------------------------------------------------------------------
__global__ __launch_bounds__(128)
void mlp_heads(const float* __restrict__ h,
               const float* __restrict__ nw1, const float* __restrict__ nb1,
               const float* __restrict__ nw2, const float* __restrict__ nb2,
               const float* __restrict__ mw1, const float* __restrict__ mb1,
               const float* __restrict__ mw2, const float* __restrict__ mb2,
               const float* __restrict__ dw1, const float* __restrict__ db1,
               const float* __restrict__ dw2, const float* __restrict__ db2,
               float* __restrict__ surv)
{
    __shared__ float hs[16 * 256];
    __shared__ float ws[128 * 33];
    __shared__ float red[16 * 128];
    __shared__ float bres[3][16];

    const int t  = threadIdx.x;
    const int r0 = blockIdx.x * 16;

#pragma unroll
    for (int l = 0; l < 32; l++) {
        int idx = t + l * 128;
        int r = idx >> 8, c = idx & 255;
        hs[r * 256 + c] = h[(size_t)(r0 + r) * 256 + c];
    }
    __syncthreads();

    for (int br = 0; br < 3; br++) {
        const float* w1 = (br == 0) ? nw1 : (br == 1) ? mw1 : dw1;
        const float* b1 = (br == 0) ? nb1 : (br == 1) ? mb1 : db1;
        const float* w2 = (br == 0) ? nw2 : (br == 1) ? mw2 : dw2;
        const float* b2 = (br == 0) ? nb2 : (br == 1) ? mb2 : db2;

        float acc[16];
        float bb = b1[t];
#pragma unroll
        for (int r = 0; r < 16; r++) acc[r] = bb;

        for (int c0 = 0; c0 < 256; c0 += 32) {
            __syncthreads();
#pragma unroll
            for (int l = 0; l < 8; l++) {
                int fidx = t + l * 128;
                int row = fidx >> 3;
                int k4  = (fidx & 7) << 2;
                float4 wv = *reinterpret_cast<const float4*>(w1 + (size_t)row * 256 + c0 + k4);
                ws[row * 33 + k4 + 0] = wv.x;
                ws[row * 33 + k4 + 1] = wv.y;
                ws[row * 33 + k4 + 2] = wv.z;
                ws[row * 33 + k4 + 3] = wv.w;
            }
            __syncthreads();
#pragma unroll
            for (int kk = 0; kk < 32; kk++) {
                float wv = ws[t * 33 + kk];
#pragma unroll
                for (int r = 0; r < 16; r++)
                    acc[r] += wv * hs[r * 256 + c0 + kk];
            }
        }

        float w2v = w2[t];
#pragma unroll
        for (int r = 0; r < 16; r++)
            red[r * 128 + t] = fmaxf(acc[r], 0.f) * w2v;
        __syncthreads();
        for (int st = 64; st > 0; st >>= 1) {
            if (t < st) {
#pragma unroll
                for (int r = 0; r < 16; r++)
                    red[r * 128 + t] += red[r * 128 + t + st];
            }
            __syncthreads();
        }
        if (t < 16) {
            float x = red[t * 128] + b2[0];
            float y;
            if (br == 0)      y = (x > 20.f) ? x : log1pf(expf(x));
            else if (br == 1) y = 1.f / (1.f + expf(-x));
            else              y = fmaxf(x, 0.f);
            bres[br][t] = y;
        }
        __syncthreads();
    }

    if (t < 16)
        surv[r0 + t] = logf(bres[0][t] + EPSV) + logf(bres[1][t] + EPSV) - bres[2][t];
}

// ---------------------------------------------------------------------------
// Host launch
// ---------------------------------------------------------------------------
extern "C" void kernel_launch(void* const* d_in, const int* in_sizes, int n_in,
                              void* d_out, int out_size)
{
    const float* x      = (const float*)d_in[0];
    const int*   mask   = (const int*)  d_in[1];
    const float* qw     = (const float*)d_in[2];
    const float* qb     = (const float*)d_in[3];
    const float* kw     = (const float*)d_in[4];
    const float* kb     = (const float*)d_in[5];
    const float* vw     = (const float*)d_in[6];
    const float* vb     = (const float*)d_in[7];
    const float* ow     = (const float*)d_in[8];
    const float* ob     = (const float*)d_in[9];
    const float* sp_w   = (const float*)d_in[10];
    const float* sp_b   = (const float*)d_in[11];
    const float* sa_in_w  = (const float*)d_in[12];
    const float* sa_in_b  = (const float*)d_in[13];
    const float* sa_out_w = (const float*)d_in[14];
    const float* sa_out_b = (const float*)d_in[15];
    const float* nw1 = (const float*)d_in[16];
    const float* nb1 = (const float*)d_in[17];
    const float* nw2 = (const float*)d_in[18];
    const float* nb2 = (const float*)d_in[19];
    const float* mw1 = (const float*)d_in[20];
    const float* mb1 = (const float*)d_in[21];
    const float* mw2 = (const float*)d_in[22];
    const float* mb2 = (const float*)d_in[23];
    const float* dw1 = (const float*)d_in[24];
    const float* db1 = (const float*)d_in[25];
    const float* dw2 = (const float*)d_in[26];
    const float* db2 = (const float*)d_in[27];

    float* out = (float*)d_out;

    float* scr = 0;
    cudaGetSymbolAddress((void**)&scr, g_scr);
    float* q    = scr;
    float* k    = q    + MS;
    float* v    = k    + MS;
    float* attn = v    + MS;
    float* sqkv = attn + MS;
    float* h0   = sqkv + MS;
    float* hatt = h0   + ISZ;
    float* h2   = hatt + ISZ;
    float* surv = h2   + ISZ;

    cudaFuncSetAttribute(flash_tf32, cudaFuncAttributeMaxDynamicSharedMemorySize, FA_SMEM);

    const int M = MROWS;   // 4096

    // ---- scorer branch ----
    gemm_tf32<<<dim3(II / 64, M / 128), 256>>>(x, sp_w, sp_b, h0, M, II, HH);
    gemm_tf32<<<dim3(HH / 64, M / 128), 256>>>(h0, sa_in_w, sa_in_b, sqkv, M, HH, II);
    flash_tf32<<<dim3(SS / 64, BB * NHEADS_SCORER), 128, FA_SMEM>>>(
        sqkv + 0, sqkv + II, sqkv + 2 * II, hatt,
        mask, (const float*)0, 0.f, SS, /*qstride=*/3 * II, /*ostride=*/II, NHEADS_SCORER);
    gemm_tf32<<<dim3(II / 64, M / 128), 256>>>(hatt, sa_out_w, sa_out_b, h2, M, II, II);
    mlp_heads<<<M / 16, 128>>>(h2, nw1, nb1, nw2, nb2, mw1, mb1, mw2, mb2,
                               dw1, db1, dw2, db2, surv);

    // ---- main branch ----
    gemm_tf32<<<dim3(HH / 64, M / 128), 256>>>(x, qw, qb, q, M, HH, HH);
    gemm_tf32<<<dim3(HH / 64, M / 128), 256>>>(x, kw, kb, k, M, HH, HH);
    gemm_tf32<<<dim3(HH / 64, M / 128), 256>>>(x, vw, vb, v, M, HH, HH);

    flash_tf32<<<dim3(SS / 64, BB * NHEADS_MAIN), 128, FA_SMEM>>>(
        q, k, v, attn, mask, surv, ALPHA, SS, /*qstride=*/HH, /*ostride=*/HH, NHEADS_MAIN);

    gemm_tf32<<<dim3(HH / 64, M / 128), 256>>>(attn, ow, ob, out, M, HH, HH);
}